// round 1
// baseline (speedup 1.0000x reference)
#include <cuda_runtime.h>
#include <cuda_bf16.h>
#include <cstdint>
#include <cfloat>

// Problem constants (fixed by setup_inputs)
#define BS   16
#define QN   1024
#define CN   92
#define TN   128

// Scratch: transposed cost Ct[b][t][q] so the JV column-scan is coalesced.
__device__ float g_Ct[BS * TN * QN];
__device__ int   g_lbl64;   // 1 if labels buffer is int64-laid-out, else int32

// ---------------------------------------------------------------------------
// Detect int64 vs int32 label layout: if int64 (little-endian, values < 92),
// every odd 32-bit word of the first 1024 entries is 0. For int32 random
// labels in [0,92) that is essentially impossible.
// ---------------------------------------------------------------------------
__global__ void detect_label_dtype(const int* __restrict__ lab32) {
    __shared__ int ok;
    if (threadIdx.x == 0) ok = 1;
    __syncthreads();
    for (int t = threadIdx.x; t < 1024; t += blockDim.x) {
        if (lab32[2 * t + 1] != 0) ok = 0;
    }
    __syncthreads();
    if (threadIdx.x == 0) g_lbl64 = ok;
}

// ---------------------------------------------------------------------------
// Cost kernel: one block per (b,q), 128 threads (one per target t).
// C[b,q,t] = |px-tx| + |py-ty| - softmax(logits[b,q])[label[b,t]]
// Writes Cb (output) and Ct (transposed scratch).
// ---------------------------------------------------------------------------
__global__ void cost_kernel(const float* __restrict__ logits,
                            const float* __restrict__ points,
                            const int*   __restrict__ lab32,
                            const float* __restrict__ tpoints,
                            float* __restrict__ outC)
{
    const int bq  = blockIdx.x;            // 0 .. BS*QN-1
    const int b   = bq >> 10;
    const int q   = bq & (QN - 1);
    const int tid = threadIdx.x;           // 0..127

    __shared__ float sl[CN];
    __shared__ float red[128];
    __shared__ float s_px, s_py;

    const float* lg = logits + (size_t)bq * CN;
    if (tid < CN) sl[tid] = lg[tid];
    if (tid == 0) { s_px = points[bq * 2]; s_py = points[bq * 2 + 1]; }
    __syncthreads();

    // max over 92 logits
    float v = (tid < CN) ? sl[tid] : -FLT_MAX;
    red[tid] = v; __syncthreads();
    #pragma unroll
    for (int s = 64; s > 0; s >>= 1) {
        if (tid < s) red[tid] = fmaxf(red[tid], red[tid + s]);
        __syncthreads();
    }
    const float mx = red[0];
    __syncthreads();

    // sum of exp
    float e = (tid < CN) ? expf(sl[tid] - mx) : 0.f;
    red[tid] = e; __syncthreads();
    #pragma unroll
    for (int s = 64; s > 0; s >>= 1) {
        if (tid < s) red[tid] += red[tid + s];
        __syncthreads();
    }
    const float inv = 1.f / red[0];

    // this thread's target
    const int lidx = b * TN + tid;
    const int lbl  = g_lbl64 ? lab32[2 * lidx] : lab32[lidx];
    const float prob = expf(sl[lbl] - mx) * inv;
    const float tx = tpoints[lidx * 2];
    const float ty = tpoints[lidx * 2 + 1];
    const float c  = fabsf(s_px - tx) + fabsf(s_py - ty) - prob;

    outC[(size_t)bq * TN + tid] = c;                      // Cb[b,q,t]
    g_Ct[((size_t)b * TN + tid) * QN + q] = c;            // Ct[b,t,q]
}

// ---------------------------------------------------------------------------
// Jonker-Volgenant (e-maxx Hungarian) per batch: n=128 rows (targets),
// m=1024 cols (queries). One block per batch, one thread per column.
// All duals in double to exactly match the numpy float64 reference.
// ---------------------------------------------------------------------------
__global__ void __launch_bounds__(1024, 1)
lsa_kernel(float* __restrict__ outRow, float* __restrict__ outCol)
{
    const int b   = blockIdx.x;
    const int tid = threadIdx.x;
    const int j   = tid + 1;                 // 1..1024 (column index, 1-based)

    __shared__ double v_[QN + 1];
    __shared__ double minv[QN + 1];
    __shared__ double u_[TN + 1];
    __shared__ int    p_[QN + 1];
    __shared__ int    way[QN + 1];
    __shared__ unsigned char used[QN + 1];
    __shared__ int    ansq[TN];
    __shared__ double wval[32];
    __shared__ int    widx[32];
    __shared__ double s_delta;
    __shared__ int    s_j0, s_j1;

    const float* C = g_Ct + (size_t)b * TN * QN;
    const double DINF = 1e300;

    v_[j] = 0.0; p_[j] = 0;
    if (tid <= TN) u_[tid] = 0.0;
    if (tid == 0) { v_[0] = 0.0; p_[0] = 0; }
    __syncthreads();

    for (int i = 1; i <= TN; ++i) {
        minv[j] = DINF; used[j] = 0;
        if (tid == 0) { p_[0] = i; used[0] = 0; s_j0 = 0; }
        __syncthreads();

        while (true) {
            const int j0 = s_j0;
            if (tid == 0) used[j0] = 1;
            __syncthreads();

            const int    i0  = p_[j0];
            const double ui0 = u_[i0];

            double mval; int midx;
            const bool isUsed = (used[j] != 0);
            if (!isUsed) {
                double cur = (double)C[(i0 - 1) * QN + (j - 1)] - ui0 - v_[j];
                if (cur < minv[j]) { minv[j] = cur; way[j] = j0; }
                mval = minv[j]; midx = j;
            } else {
                mval = DINF * 2.0; midx = QN + 2;
            }

            // block argmin (lowest index wins ties, like np.argmin)
            #pragma unroll
            for (int off = 16; off > 0; off >>= 1) {
                double ov = __shfl_down_sync(0xffffffffu, mval, off);
                int    oi = __shfl_down_sync(0xffffffffu, midx, off);
                if (ov < mval || (ov == mval && oi < midx)) { mval = ov; midx = oi; }
            }
            const int lane = tid & 31, wid = tid >> 5;
            if (lane == 0) { wval[wid] = mval; widx[wid] = midx; }
            __syncthreads();
            if (wid == 0) {
                mval = wval[lane]; midx = widx[lane];
                #pragma unroll
                for (int off = 16; off > 0; off >>= 1) {
                    double ov = __shfl_down_sync(0xffffffffu, mval, off);
                    int    oi = __shfl_down_sync(0xffffffffu, midx, off);
                    if (ov < mval || (ov == mval && oi < midx)) { mval = ov; midx = oi; }
                }
                if (lane == 0) { s_delta = mval; s_j1 = midx; }
            }
            __syncthreads();

            const double delta = s_delta;
            const int    j1    = s_j1;

            if (isUsed) { u_[p_[j]] += delta; v_[j] -= delta; }
            else        { minv[j] -= delta; }
            if (tid == 0) { u_[p_[0]] += delta; v_[0] -= delta; s_j0 = j1; }
            __syncthreads();

            if (p_[j1] == 0) break;
        }

        // augment (serial, thread 0)
        if (tid == 0) {
            int j0 = s_j0;
            while (j0) { int jw = way[j0]; p_[j0] = p_[jw]; j0 = jw; }
        }
        __syncthreads();
    }

    // extract assignment: ans[row-1] = col-1 for p[col] > 0
    if (p_[j] > 0) ansq[p_[j] - 1] = j - 1;
    __syncthreads();

    // argsort(ans) via rank counting (values are distinct)
    if (tid < TN) {
        const int a = ansq[tid];
        int r = 0;
        #pragma unroll 8
        for (int s = 0; s < TN; ++s) r += (ansq[s] < a);
        outRow[b * TN + r] = (float)a;      // sorted query indices
        outCol[b * TN + r] = (float)tid;    // corresponding target indices
    }
}

// ---------------------------------------------------------------------------
extern "C" void kernel_launch(void* const* d_in, const int* in_sizes, int n_in,
                              void* d_out, int out_size)
{
    const float* logits  = (const float*)d_in[0];   // [16,1024,92]
    const float* points  = (const float*)d_in[1];   // [16,1024,2]
    const int*   labels  = (const int*)  d_in[2];   // [16,128] int32 or int64
    const float* tpoints = (const float*)d_in[3];   // [16,128,2]

    float* out = (float*)d_out;
    float* outC   = out;                              // 16*1024*128 = 2097152
    float* outRow = out + (size_t)BS * QN * TN;       // 16*128 = 2048
    float* outCol = outRow + BS * TN;                 // 16*128 = 2048

    detect_label_dtype<<<1, 256>>>(labels);
    cost_kernel<<<BS * QN, 128>>>(logits, points, labels, tpoints, outC);
    lsa_kernel<<<BS, 1024>>>(outRow, outCol);
}

// round 2
// speedup vs baseline: 2.0074x; 2.0074x over previous
#include <cuda_runtime.h>
#include <cuda_bf16.h>
#include <cstdint>
#include <cfloat>

#define BS   16
#define QN   1024
#define CN   92
#define TN   128

// Transposed cost Ct[b][t][q] so the JV row scan is float4-coalesced.
__device__ float g_Ct[BS * TN * QN];
__device__ int   g_lbl64;

// ---------------------------------------------------------------------------
// Detect int64 vs int32 label layout (odd 32-bit words all zero => int64).
// ---------------------------------------------------------------------------
__global__ void detect_label_dtype(const int* __restrict__ lab32) {
    __shared__ int ok;
    if (threadIdx.x == 0) ok = 1;
    __syncthreads();
    for (int t = threadIdx.x; t < 1024; t += blockDim.x)
        if (lab32[2 * t + 1] != 0) ok = 0;
    __syncthreads();
    if (threadIdx.x == 0) g_lbl64 = ok;
}

// ---------------------------------------------------------------------------
// Cost kernel: one WARP per query (barrier-light). Block = 8 warps = 8 queries.
// ---------------------------------------------------------------------------
__global__ void __launch_bounds__(256)
cost_kernel(const float* __restrict__ logits,
            const float* __restrict__ points,
            const int*   __restrict__ lab32,
            const float* __restrict__ tpoints,
            float* __restrict__ outC)
{
    const int warp = threadIdx.x >> 5, lane = threadIdx.x & 31;
    const int bq = blockIdx.x * 8 + warp;      // 0..16383
    const int b  = bq >> 10, q = bq & 1023;

    __shared__ float slog[8][96];
    __shared__ int   slbl[TN];
    __shared__ float stx[TN], sty[TN];

    if (threadIdx.x < TN) {
        const int lidx = b * TN + threadIdx.x;
        slbl[threadIdx.x] = g_lbl64 ? lab32[2 * lidx] : lab32[lidx];
        stx[threadIdx.x]  = tpoints[lidx * 2];
        sty[threadIdx.x]  = tpoints[lidx * 2 + 1];
    }

    const float* lg = logits + (size_t)bq * CN;
    const float a  = lg[lane];
    const float bb = lg[lane + 32];
    const float c  = (lane < 28) ? lg[lane + 64] : -FLT_MAX;
    slog[warp][lane]      = a;
    slog[warp][lane + 32] = bb;
    if (lane < 28) slog[warp][lane + 64] = c;

    float mx = fmaxf(a, fmaxf(bb, c));
    #pragma unroll
    for (int o = 16; o > 0; o >>= 1) mx = fmaxf(mx, __shfl_xor_sync(0xffffffffu, mx, o));

    float e = expf(a - mx) + expf(bb - mx) + ((lane < 28) ? expf(c - mx) : 0.f);
    #pragma unroll
    for (int o = 16; o > 0; o >>= 1) e += __shfl_xor_sync(0xffffffffu, e, o);
    const float inv = 1.f / e;

    const float px = __ldg(points + bq * 2);
    const float py = __ldg(points + bq * 2 + 1);
    __syncthreads();   // slbl/stx/sty + slog visible

    #pragma unroll
    for (int c2 = 0; c2 < 4; c2++) {
        const int t = c2 * 32 + lane;
        const float prob = expf(slog[warp][slbl[t]] - mx) * inv;
        const float cost = fabsf(px - stx[t]) + fabsf(py - sty[t]) - prob;
        outC[(size_t)bq * TN + t] = cost;                 // Cb[b,q,t]
        g_Ct[((size_t)b * TN + t) * QN + q] = cost;       // Ct[b,t,q]
    }
}

// ---------------------------------------------------------------------------
// Order-preserving double -> uint64 key
// ---------------------------------------------------------------------------
__device__ __forceinline__ unsigned long long dkey(double x) {
    unsigned long long u = __double_as_longlong(x);
    return (u & 0x8000000000000000ULL) ? ~u : (u ^ 0x8000000000000000ULL);
}

// ---------------------------------------------------------------------------
// JV / e-maxx Hungarian. One block per batch, 256 threads, 4 columns/thread.
// minv & v live in registers; argmin via one shared atomicMin on packed key
// (low 11 bits = column index -> lowest-index tie-break like np.argmin);
// exact double delta is broadcast by the winning thread. 2 barriers/step.
// ---------------------------------------------------------------------------
__global__ void __launch_bounds__(256, 1)
lsa_kernel(float* __restrict__ outRow, float* __restrict__ outCol)
{
    const int b = blockIdx.x, tid = threadIdx.x;

    __shared__ double u_[TN + 1];
    __shared__ int    p_[QN + 1];
    __shared__ int    way_[QN + 1];
    __shared__ unsigned long long s_key[2];
    __shared__ double s_delta;
    __shared__ int    ansq[TN];

    const float* C = g_Ct + (size_t)b * TN * QN;
    const double DINF = 1e300;

    #pragma unroll
    for (int k = 0; k < 4; k++) p_[tid * 4 + k + 1] = 0;
    if (tid == 0) { p_[0] = 0; s_key[0] = ~0ULL; s_key[1] = ~0ULL; }
    if (tid <= TN) u_[tid] = 0.0;
    __syncthreads();

    double v[4] = {0.0, 0.0, 0.0, 0.0};
    int par = 0;

    for (int i = 1; i <= TN; ++i) {
        double minv[4] = {DINF, DINF, DINF, DINF};
        int usedm = 0;
        if (tid == 0) p_[0] = i;
        __syncthreads();               // row start: p_/u_/augment visible

        int j0 = 0;
        while (true) {
            const int    i0  = p_[j0];
            const double ui0 = u_[i0];

            const float4 cc = __ldg((const float4*)(C + (size_t)(i0 - 1) * QN) + tid);
            const float cf[4] = {cc.x, cc.y, cc.z, cc.w};

            unsigned long long lkey = ~0ULL;
            #pragma unroll
            for (int k = 0; k < 4; k++) {
                if (!((usedm >> k) & 1)) {
                    const int j = tid * 4 + k + 1;
                    const double cur = (double)cf[k] - ui0 - v[k];
                    if (cur < minv[k]) { minv[k] = cur; way_[j] = j0; }
                    const unsigned long long kk =
                        (dkey(minv[k]) & ~2047ULL) | (unsigned long long)j;
                    if (kk < lkey) lkey = kk;
                }
            }
            if (lkey != ~0ULL) atomicMin(&s_key[par], lkey);
            __syncthreads();           // B1: argmin complete

            const unsigned long long kmin = s_key[par];
            const int j1   = (int)(kmin & 2047ULL);
            const int kown = j1 - 1 - tid * 4;
            if (kown >= 0 && kown < 4) s_delta = minv[kown];   // exact double
            if (tid == 0) s_key[par ^ 1] = ~0ULL;              // reset other slot
            const int pj1 = p_[j1];
            __syncthreads();           // B2: delta ready

            const double delta = s_delta;
            #pragma unroll
            for (int k = 0; k < 4; k++) {
                if ((usedm >> k) & 1) { u_[p_[tid * 4 + k + 1]] += delta; v[k] -= delta; }
                else                  { minv[k] -= delta; }
            }
            if (kown >= 0 && kown < 4) usedm |= (1 << kown);   // j1 used from next step
            if (tid == 0) u_[i] += delta;                      // virtual column 0

            j0 = j1; par ^= 1;
            if (pj1 == 0) break;
            // NO barrier here: next scan reads only u_[p_[j1]], which no update
            // of this step writes (j1 was free), plus thread-private v/minv.
        }

        __syncthreads();               // updates settled before augment
        if (tid == 0) {
            int jj = j0;
            while (jj) { const int jw = way_[jj]; p_[jj] = p_[jw]; jj = jw; }
        }
        // next row's top barrier publishes the augment
    }

    __syncthreads();
    #pragma unroll
    for (int k = 0; k < 4; k++) {
        const int j = tid * 4 + k + 1;
        if (p_[j] > 0) ansq[p_[j] - 1] = j - 1;
    }
    __syncthreads();

    if (tid < TN) {
        const int a = ansq[tid];
        int r = 0;
        #pragma unroll 8
        for (int s = 0; s < TN; ++s) r += (ansq[s] < a);
        outRow[b * TN + r] = (float)a;
        outCol[b * TN + r] = (float)tid;
    }
}

// ---------------------------------------------------------------------------
extern "C" void kernel_launch(void* const* d_in, const int* in_sizes, int n_in,
                              void* d_out, int out_size)
{
    const float* logits  = (const float*)d_in[0];
    const float* points  = (const float*)d_in[1];
    const int*   labels  = (const int*)  d_in[2];
    const float* tpoints = (const float*)d_in[3];

    float* out    = (float*)d_out;
    float* outC   = out;
    float* outRow = out + (size_t)BS * QN * TN;
    float* outCol = outRow + BS * TN;

    detect_label_dtype<<<1, 256>>>(labels);
    cost_kernel<<<BS * QN / 8, 256>>>(logits, points, labels, tpoints, outC);
    lsa_kernel<<<BS, 256>>>(outRow, outCol);
}